// round 1
// baseline (speedup 1.0000x reference)
#include <cuda_runtime.h>
#include <math.h>

#define T_TOK 1024
#define HID   2048
#define NE    32
#define TOPK  6
#define NGRP  8
#define TGRP  3
#define IR    1408          // routed intermediate
#define IS    2816          // shared intermediate (I * NSH)
#define CAP   384
#define RSCALE 16.0f

#define BM 64
#define BN 64
#define BK 16

// ---------------- scratch (device globals: allocation-free) ----------------
__device__ int   g_topk_idx[T_TOK * TOPK];
__device__ float g_topk_w  [T_TOK * TOPK];
__device__ int   g_cnt     [NE];
__device__ int   g_rowtok  [NE * CAP];
__device__ int   g_slot    [T_TOK * TOPK];
__device__ float g_act     [NE * CAP * IR];    // 69 MB: routed silu(g)*u
__device__ float g_y       [NE * CAP * HID];   // 100 MB: routed expert outputs
__device__ float g_acts    [T_TOK * IS];       // 11.5 MB: shared silu(g)*u

// ---------------- gate + routing (one block per token) ----------------
__global__ void k_gate(const float* __restrict__ x, const float* __restrict__ gw) {
    int t = blockIdx.x;
    __shared__ float xs[HID];
    __shared__ float lg[NE];
    const float* xr = x + (size_t)t * HID;
    for (int i = threadIdx.x; i < HID; i += 256) xs[i] = xr[i];
    __syncthreads();

    // 8 threads per expert compute the dot product
    int e = threadIdx.x >> 3, j = threadIdx.x & 7;
    const float* w = gw + (size_t)e * HID;
    float s = 0.f;
    for (int i = j * 4; i < HID; i += 32) {
        float4 xv = *(const float4*)(xs + i);
        float4 wv = *(const float4*)(w + i);
        s += xv.x * wv.x + xv.y * wv.y + xv.z * wv.z + xv.w * wv.w;
    }
    #pragma unroll
    for (int off = 4; off; off >>= 1) s += __shfl_down_sync(0xffffffffu, s, off, 8);
    if (j == 0) lg[e] = s;
    __syncthreads();

    if (threadIdx.x == 0) {
        // group scores = max over each group of 4
        float gsc[NGRP]; int keep[NGRP];
        #pragma unroll
        for (int g2 = 0; g2 < NGRP; g2++) {
            float m4 = lg[g2 * 4];
            m4 = fmaxf(m4, lg[g2 * 4 + 1]);
            m4 = fmaxf(m4, lg[g2 * 4 + 2]);
            m4 = fmaxf(m4, lg[g2 * 4 + 3]);
            gsc[g2] = m4; keep[g2] = 0;
        }
        // top-3 groups (strict >, ascending scan == lax.top_k tie rule)
        for (int it = 0; it < TGRP; it++) {
            float best = -INFINITY; int bi = 0;
            for (int g2 = 0; g2 < NGRP; g2++)
                if (!keep[g2] && gsc[g2] > best) { best = gsc[g2]; bi = g2; }
            keep[bi] = 1;
        }
        // masked scores (non-kept -> 0.0 !) then softmax over all 32
        float sc[NE]; float mx = -INFINITY;
        for (int e2 = 0; e2 < NE; e2++) {
            float v = keep[e2 >> 2] ? lg[e2] : 0.0f;
            sc[e2] = v; mx = fmaxf(mx, v);
        }
        float sum = 0.f;
        for (int e2 = 0; e2 < NE; e2++) { float p = expf(sc[e2] - mx); sc[e2] = p; sum += p; }
        // top-6 of probs (unnormalized exp has identical ordering & ties)
        unsigned taken = 0u;
        for (int it = 0; it < TOPK; it++) {
            float best = -1.f; int bi = 0;
            for (int e2 = 0; e2 < NE; e2++)
                if (!((taken >> e2) & 1u) && sc[e2] > best) { best = sc[e2]; bi = e2; }
            taken |= 1u << bi;
            g_topk_idx[t * TOPK + it] = bi;
            g_topk_w  [t * TOPK + it] = (best / sum) * RSCALE;
        }
    }
}

// ---------------- dispatch: flat-order capacity positions (warp e scans all) ----------------
__global__ void k_dispatch() {
    int w = threadIdx.x >> 5, lane = threadIdx.x & 31;
    int count = 0;
    for (int base = 0; base < T_TOK * TOPK; base += 32) {
        int idx = g_topk_idx[base + lane];
        unsigned m = __ballot_sync(0xffffffffu, idx == w);
        if (idx == w) {
            int pos = count + __popc(m & ((1u << lane) - 1u));
            int s = -1;
            if (pos < CAP) { s = w * CAP + pos; g_rowtok[s] = (base + lane) / TOPK; }
            g_slot[base + lane] = s;
        }
        count += __popc(m);
    }
    if (lane == 0) g_cnt[w] = count;
}

// ---------------- GEMM: A[rows,K] @ B[K,2*Nhalf] with fused silu(g)*u ----------------
__device__ __forceinline__ void gemm_gateup(
    const float* __restrict__ A, const int* __restrict__ rowtok,
    const int* __restrict__ cnt, const float* __restrict__ B,
    float* __restrict__ Cout, int lda, int Kdim, int Nhalf, int ldb,
    int tilesM, int cap)
{
    int e  = blockIdx.y / tilesM;
    int mt = blockIdx.y - e * tilesM;
    int rows = cnt ? min(cnt[e], cap) : cap;
    int m0 = mt * BM;
    if (m0 >= rows) return;

    __shared__ float As[BK][BM + 4];
    __shared__ float Bg[BK][BN];
    __shared__ float Bu[BK][BN];
    __shared__ int   rix[BM];

    int tid = threadIdx.x;
    if (tid < BM) {
        int gm = m0 + tid;
        rix[tid] = (gm < rows) ? (rowtok ? rowtok[e * cap + gm] : gm) : -1;
    }
    __syncthreads();

    int ar = tid >> 2, ak = (tid & 3) << 2;    // A loader: row, k-offset
    int br = tid >> 4, bn = (tid & 15) << 2;   // B loader: k-row, n-offset
    int tx = tid & 15, ty = tid >> 4;          // compute microtile coords

    int rt = rix[ar];
    const float* Ap = (rt >= 0) ? (A + (size_t)rt * lda + ak) : A;
    bool aval = (rt >= 0);
    const float* Bp = B + (size_t)e * Kdim * ldb + (size_t)br * ldb
                        + (size_t)blockIdx.x * BN + bn;

    float accg[16], accu[16];
    #pragma unroll
    for (int i = 0; i < 16; i++) { accg[i] = 0.f; accu[i] = 0.f; }

    for (int k0 = 0; k0 < Kdim; k0 += BK) {
        float4 av = make_float4(0.f, 0.f, 0.f, 0.f);
        if (aval) av = *(const float4*)(Ap + k0);
        const float* bp = Bp + (size_t)k0 * ldb;
        float4 bgv = *(const float4*)bp;
        float4 buv = *(const float4*)(bp + Nhalf);
        __syncthreads();
        As[ak][ar] = av.x; As[ak + 1][ar] = av.y; As[ak + 2][ar] = av.z; As[ak + 3][ar] = av.w;
        *(float4*)&Bg[br][bn] = bgv;
        *(float4*)&Bu[br][bn] = buv;
        __syncthreads();
        #pragma unroll
        for (int kk = 0; kk < BK; kk++) {
            float4 a  = *(const float4*)&As[kk][ty << 2];
            float4 bg = *(const float4*)&Bg[kk][tx << 2];
            float4 bu = *(const float4*)&Bu[kk][tx << 2];
            float aa[4] = {a.x, a.y, a.z, a.w};
            float gg[4] = {bg.x, bg.y, bg.z, bg.w};
            float uu[4] = {bu.x, bu.y, bu.z, bu.w};
            #pragma unroll
            for (int i = 0; i < 4; i++)
                #pragma unroll
                for (int jj = 0; jj < 4; jj++) {
                    accg[i * 4 + jj] += aa[i] * gg[jj];
                    accu[i * 4 + jj] += aa[i] * uu[jj];
                }
        }
    }

    float* Ce = Cout + (size_t)e * cap * Nhalf + (size_t)blockIdx.x * BN + (tx << 2);
    #pragma unroll
    for (int i = 0; i < 4; i++) {
        int gm = m0 + (ty << 2) + i;
        if (gm >= rows) break;
        float4 o; float g, u;
        g = accg[i * 4 + 0]; u = accu[i * 4 + 0]; o.x = u * g / (1.f + expf(-g));
        g = accg[i * 4 + 1]; u = accu[i * 4 + 1]; o.y = u * g / (1.f + expf(-g));
        g = accg[i * 4 + 2]; u = accu[i * 4 + 2]; o.z = u * g / (1.f + expf(-g));
        g = accg[i * 4 + 3]; u = accu[i * 4 + 3]; o.w = u * g / (1.f + expf(-g));
        *(float4*)(Ce + (size_t)gm * Nhalf) = o;
    }
}

// ---------------- plain GEMM: A[rows,K] @ B[K,N] ----------------
__device__ __forceinline__ void gemm_plain(
    const float* __restrict__ A, const int* __restrict__ cnt,
    const float* __restrict__ B, float* __restrict__ Cout,
    int lda, int Kdim, int N, int ldb, int tilesM, int cap)
{
    int e  = blockIdx.y / tilesM;
    int mt = blockIdx.y - e * tilesM;
    int rows = cnt ? min(cnt[e], cap) : cap;
    int m0 = mt * BM;
    if (m0 >= rows) return;

    __shared__ float As[BK][BM + 4];
    __shared__ float Bs[BK][BN];

    int tid = threadIdx.x;
    int ar = tid >> 2, ak = (tid & 3) << 2;
    int br = tid >> 4, bn = (tid & 15) << 2;
    int tx = tid & 15, ty = tid >> 4;

    const float* Ap = A + (size_t)e * cap * lda + (size_t)(m0 + ar) * lda + ak;
    const float* Bp = B + (size_t)e * Kdim * ldb + (size_t)br * ldb
                        + (size_t)blockIdx.x * BN + bn;

    float acc[16];
    #pragma unroll
    for (int i = 0; i < 16; i++) acc[i] = 0.f;

    for (int k0 = 0; k0 < Kdim; k0 += BK) {
        float4 av = *(const float4*)(Ap + k0);
        float4 bv = *(const float4*)(Bp + (size_t)k0 * ldb);
        __syncthreads();
        As[ak][ar] = av.x; As[ak + 1][ar] = av.y; As[ak + 2][ar] = av.z; As[ak + 3][ar] = av.w;
        *(float4*)&Bs[br][bn] = bv;
        __syncthreads();
        #pragma unroll
        for (int kk = 0; kk < BK; kk++) {
            float4 a = *(const float4*)&As[kk][ty << 2];
            float4 b = *(const float4*)&Bs[kk][tx << 2];
            float aa[4] = {a.x, a.y, a.z, a.w};
            float bb[4] = {b.x, b.y, b.z, b.w};
            #pragma unroll
            for (int i = 0; i < 4; i++)
                #pragma unroll
                for (int jj = 0; jj < 4; jj++)
                    acc[i * 4 + jj] += aa[i] * bb[jj];
        }
    }

    float* Ce = Cout + (size_t)e * cap * N + (size_t)blockIdx.x * BN + (tx << 2);
    #pragma unroll
    for (int i = 0; i < 4; i++) {
        int gm = m0 + (ty << 2) + i;
        if (gm >= rows) break;
        float4 o = make_float4(acc[i * 4], acc[i * 4 + 1], acc[i * 4 + 2], acc[i * 4 + 3]);
        *(float4*)(Ce + (size_t)gm * N) = o;
    }
}

// ---------------- wrappers binding device-global scratch ----------------
__global__ void k_gemm1_routed(const float* __restrict__ x, const float* __restrict__ wgu) {
    gemm_gateup(x, g_rowtok, g_cnt, wgu, g_act, HID, HID, IR, 2 * IR, CAP / BM, CAP);
}
__global__ void k_gemm1_shared(const float* __restrict__ x, const float* __restrict__ wsgu) {
    gemm_gateup(x, nullptr, nullptr, wsgu, g_acts, HID, HID, IS, 2 * IS, T_TOK / BM, T_TOK);
}
__global__ void k_gemm2_routed(const float* __restrict__ wd) {
    gemm_plain(g_act, g_cnt, wd, g_y, IR, IR, HID, HID, CAP / BM, CAP);
}
__global__ void k_gemm2_shared(float* __restrict__ out, const float* __restrict__ wsd) {
    gemm_plain(g_acts, nullptr, wsd, out, IS, IS, HID, HID, T_TOK / BM, T_TOK);
}

// ---------------- combine: out[t] = shared[t] + sum_k w_k * y[slot_k] ----------------
__global__ void k_combine(float* __restrict__ out) {
    int idx = blockIdx.x * 256 + threadIdx.x;      // one float4 per thread
    int t = idx >> 9;                              // 512 float4 per token
    int h = (idx & 511) << 2;
    float* op = out + (size_t)t * HID + h;
    float4 acc = *(float4*)op;                     // shared-expert value already written
    #pragma unroll
    for (int k = 0; k < TOPK; k++) {
        int s = g_slot[t * TOPK + k];
        if (s >= 0) {
            float wv = g_topk_w[t * TOPK + k];
            float4 y = *(const float4*)(g_y + (size_t)s * HID + h);
            acc.x += wv * y.x; acc.y += wv * y.y; acc.z += wv * y.z; acc.w += wv * y.w;
        }
    }
    *(float4*)op = acc;
}

// ---------------- entry ----------------
extern "C" void kernel_launch(void* const* d_in, const int* in_sizes, int n_in,
                              void* d_out, int out_size) {
    const float* x    = (const float*)d_in[0];   // [1,1024,2048]
    const float* gw   = (const float*)d_in[1];   // [32,2048]
    const float* wgu  = (const float*)d_in[2];   // [32,2048,2816]
    const float* wd   = (const float*)d_in[3];   // [32,1408,2048]
    const float* wsgu = (const float*)d_in[4];   // [2048,5632]
    const float* wsd  = (const float*)d_in[5];   // [2816,2048]
    float* out = (float*)d_out;                  // [1024,2048] fp32

    k_gate    <<<T_TOK, 256>>>(x, gw);
    k_dispatch<<<1, 1024>>>();
    k_gemm1_routed<<<dim3(IR  / BN, NE * (CAP / BM)), 256>>>(x, wgu);
    k_gemm2_routed<<<dim3(HID / BN, NE * (CAP / BM)), 256>>>(wd);
    k_gemm1_shared<<<dim3(IS  / BN, T_TOK / BM), 256>>>(x, wsgu);
    k_gemm2_shared<<<dim3(HID / BN, T_TOK / BM), 256>>>(out, wsd);
    k_combine <<<(T_TOK * HID / 4) / 256, 256>>>(out);
}